// round 5
// baseline (speedup 1.0000x reference)
#include <cuda_runtime.h>
#include <math.h>

// ---------------------------------------------------------------------------
// Persistent fused kernel, smem-staged for perfectly coalesced global access.
//
// Warp tile = 128 rows = 3584 B = 224 float4:
//   load phase : each lane, 7x coalesced LDG.128 (lane + 32j) -> STS.128
//   compute    : each lane reads rows [4*lane, 4*lane+4) = 7x LDS.128 at byte
//                offset lane*112 (conflict-free), 28 FMAs + 4 sigmoids,
//                1x coalesced STG.128
//
// Prologue: thread 0 composes the 5 tiny linears (7->5->4->3->2->1) into one
// 7->1 affine map with fully-unrolled scalar code (no local memory).
// ---------------------------------------------------------------------------

#define WARPS_PER_BLOCK 8

__global__ void __launch_bounds__(256)
mlp_smem_kernel(const float* __restrict__ X, float* __restrict__ out, int nrows,
                const float* __restrict__ W1, const float* __restrict__ b1,
                const float* __restrict__ W2, const float* __restrict__ b2,
                const float* __restrict__ W3, const float* __restrict__ b3,
                const float* __restrict__ W4, const float* __restrict__ b4,
                const float* __restrict__ W5, const float* __restrict__ b5)
{
    __shared__ float4 s_tile[WARPS_PER_BLOCK][224];   // 28 KB
    __shared__ float  s_weff[8];

    if (threadIdx.x == 0) {
        // ---- fully unrolled compose, scalar registers only ----
        const float c50 = W5[0], c51 = W5[1];

        const float w45_0 = fmaf(W4[0], c50, W4[1] * c51);
        const float w45_1 = fmaf(W4[2], c50, W4[3] * c51);
        const float w45_2 = fmaf(W4[4], c50, W4[5] * c51);

        const float w345_0 = fmaf(W3[0],  w45_0, fmaf(W3[1],  w45_1, W3[2]  * w45_2));
        const float w345_1 = fmaf(W3[3],  w45_0, fmaf(W3[4],  w45_1, W3[5]  * w45_2));
        const float w345_2 = fmaf(W3[6],  w45_0, fmaf(W3[7],  w45_1, W3[8]  * w45_2));
        const float w345_3 = fmaf(W3[9],  w45_0, fmaf(W3[10], w45_1, W3[11] * w45_2));

        const float w2345_0 = fmaf(W2[0],  w345_0, fmaf(W2[1],  w345_1, fmaf(W2[2],  w345_2, W2[3]  * w345_3)));
        const float w2345_1 = fmaf(W2[4],  w345_0, fmaf(W2[5],  w345_1, fmaf(W2[6],  w345_2, W2[7]  * w345_3)));
        const float w2345_2 = fmaf(W2[8],  w345_0, fmaf(W2[9],  w345_1, fmaf(W2[10], w345_2, W2[11] * w345_3)));
        const float w2345_3 = fmaf(W2[12], w345_0, fmaf(W2[13], w345_1, fmaf(W2[14], w345_2, W2[15] * w345_3)));
        const float w2345_4 = fmaf(W2[16], w345_0, fmaf(W2[17], w345_1, fmaf(W2[18], w345_2, W2[19] * w345_3)));

        #pragma unroll
        for (int i = 0; i < 7; i++) {
            s_weff[i] = fmaf(W1[i*5 + 0], w2345_0,
                        fmaf(W1[i*5 + 1], w2345_1,
                        fmaf(W1[i*5 + 2], w2345_2,
                        fmaf(W1[i*5 + 3], w2345_3,
                             W1[i*5 + 4] * w2345_4))));
        }

        float be = b5[0];
        be = fmaf(b4[0], c50, be);
        be = fmaf(b4[1], c51, be);
        be = fmaf(b3[0], w45_0, be);
        be = fmaf(b3[1], w45_1, be);
        be = fmaf(b3[2], w45_2, be);
        be = fmaf(b2[0], w345_0, be);
        be = fmaf(b2[1], w345_1, be);
        be = fmaf(b2[2], w345_2, be);
        be = fmaf(b2[3], w345_3, be);
        be = fmaf(b1[0], w2345_0, be);
        be = fmaf(b1[1], w2345_1, be);
        be = fmaf(b1[2], w2345_2, be);
        be = fmaf(b1[3], w2345_3, be);
        be = fmaf(b1[4], w2345_4, be);
        s_weff[7] = be;
    }
    __syncthreads();

    const float w0 = s_weff[0], w1 = s_weff[1], w2 = s_weff[2], w3 = s_weff[3];
    const float w4 = s_weff[4], w5 = s_weff[5], w6 = s_weff[6], be = s_weff[7];

    const int wid  = threadIdx.x >> 5;
    const int lane = threadIdx.x & 31;

    const long long nchunks = (long long)(nrows >> 7);          // 128 rows/chunk
    const long long gwarp   = (long long)blockIdx.x * WARPS_PER_BLOCK + wid;
    const long long nwarps  = (long long)gridDim.x * WARPS_PER_BLOCK;

    float4* sw = s_tile[wid];
    const float4* Xv = reinterpret_cast<const float4*>(X);
    float4* outv = reinterpret_cast<float4*>(out);

    for (long long c = gwarp; c < nchunks; c += nwarps) {
        const float4* src = Xv + c * 224;

        // ---- coalesced load phase: 7x LDG.128 -> STS.128 ----
        #pragma unroll
        for (int j = 0; j < 7; j++) {
            sw[lane + 32 * j] = __ldcs(src + lane + 32 * j);
        }
        __syncwarp();

        // ---- compute phase: lane handles 4 rows at byte offset lane*112 ----
        const float4* xq = reinterpret_cast<const float4*>(
                               reinterpret_cast<const float*>(sw) + lane * 28);
        float4 q0 = xq[0], q1 = xq[1], q2 = xq[2], q3 = xq[3];
        float4 q4 = xq[4], q5 = xq[5], q6 = xq[6];

        float f[28];
        f[0]=q0.x; f[1]=q0.y; f[2]=q0.z; f[3]=q0.w;
        f[4]=q1.x; f[5]=q1.y; f[6]=q1.z; f[7]=q1.w;
        f[8]=q2.x; f[9]=q2.y; f[10]=q2.z; f[11]=q2.w;
        f[12]=q3.x; f[13]=q3.y; f[14]=q3.z; f[15]=q3.w;
        f[16]=q4.x; f[17]=q4.y; f[18]=q4.z; f[19]=q4.w;
        f[20]=q5.x; f[21]=q5.y; f[22]=q5.z; f[23]=q5.w;
        f[24]=q6.x; f[25]=q6.y; f[26]=q6.z; f[27]=q6.w;

        float r[4];
        #pragma unroll
        for (int r4 = 0; r4 < 4; r4++) {
            const float* x = f + r4 * 7;
            float z = be;
            z = fmaf(x[0], w0, z);
            z = fmaf(x[1], w1, z);
            z = fmaf(x[2], w2, z);
            z = fmaf(x[3], w3, z);
            z = fmaf(x[4], w4, z);
            z = fmaf(x[5], w5, z);
            z = fmaf(x[6], w6, z);
            r[r4] = 1.0f / (1.0f + __expf(-z));
        }

        float4 o;
        o.x = r[0]; o.y = r[1]; o.z = r[2]; o.w = r[3];
        // chunk c covers row-quads [c*32, c*32+32); lane stores quad c*32+lane
        __stcs(outv + c * 32 + lane, o);

        __syncwarp();   // protect smem tile before next iteration overwrites
    }

    // Tail rows (nrows % 128) — zero for 4M rows; kept for safety.
    if (blockIdx.x == 0 && wid == 0 && lane == 0) {
        for (long long rr = nchunks << 7; rr < nrows; rr++) {
            const float* x = X + rr * 7;
            float z = be;
            z = fmaf(x[0], w0, z);
            z = fmaf(x[1], w1, z);
            z = fmaf(x[2], w2, z);
            z = fmaf(x[3], w3, z);
            z = fmaf(x[4], w4, z);
            z = fmaf(x[5], w5, z);
            z = fmaf(x[6], w6, z);
            out[rr] = 1.0f / (1.0f + __expf(-z));
        }
    }
}

extern "C" void kernel_launch(void* const* d_in, const int* in_sizes, int n_in,
                              void* d_out, int out_size)
{
    const float* X  = (const float*)d_in[0];
    const float* W1 = (const float*)d_in[1];
    const float* b1 = (const float*)d_in[2];
    const float* W2 = (const float*)d_in[3];
    const float* b2 = (const float*)d_in[4];
    const float* W3 = (const float*)d_in[5];
    const float* b3 = (const float*)d_in[6];
    const float* W4 = (const float*)d_in[7];
    const float* b4 = (const float*)d_in[8];
    const float* W5 = (const float*)d_in[9];
    const float* b5 = (const float*)d_in[10];
    float* out = (float*)d_out;

    int nrows = in_sizes[0] / 7;

    // Ask for max shared-memory carveout so 6 blocks x 28KB fit per SM.
    static bool attr_done = false;
    if (!attr_done) {
        cudaFuncSetAttribute(mlp_smem_kernel,
                             cudaFuncAttributePreferredSharedMemoryCarveout, 100);
        attr_done = true;
    }

    int sms = 0;
    if (cudaDeviceGetAttribute(&sms, cudaDevAttrMultiProcessorCount, 0) != cudaSuccess || sms <= 0)
        sms = 148;
    int blocks = sms * 6;

    mlp_smem_kernel<<<blocks, 256>>>(X, out, nrows,
                                     W1, b1, W2, b2, W3, b3, W4, b4, W5, b5);
}

// round 6
// speedup vs baseline: 1.2102x; 1.2102x over previous
#include <cuda_runtime.h>
#include <math.h>
#include <stdint.h>

// ---------------------------------------------------------------------------
// Persistent TMA-pipelined kernel.
//   Stage = 1024 rows = 28672 B. 4-deep mbarrier pipeline in dynamic smem.
//   Producer (thread 0): cp.async.bulk HBM->SMEM (async proxy: no per-lane
//   L1tex wavefronts). Consumers (256 thr): 4 rows each via LDS (tid*112,
//   conflict-free), 28 FMA + sigmoid, 1 coalesced STG.128.
//   Prologue: thread 0 composes the 5 tiny linears into one 7->1 affine map
//   (fully unrolled scalar code) while the first TMAs are in flight.
// ---------------------------------------------------------------------------

#define NSTAGE       4
#define STAGE_QUADS  256                    // row-quads per stage
#define STAGE_BYTES  (STAGE_QUADS * 112)    // 28672 B

__device__ __forceinline__ uint32_t smem_u32(const void* p) {
    uint32_t a;
    asm("{ .reg .u64 t; cvta.to.shared.u64 t, %1; cvt.u32.u64 %0, t; }"
        : "=r"(a) : "l"(p));
    return a;
}

#define MBAR_INIT(addr, cnt) \
    asm volatile("mbarrier.init.shared.b64 [%0], %1;" :: "r"(addr), "r"(cnt) : "memory")

#define MBAR_EXPECT_TX(addr, bytes) \
    asm volatile("mbarrier.arrive.expect_tx.shared.b64 _, [%0], %1;" \
                 :: "r"(addr), "r"(bytes) : "memory")

#define MBAR_ARRIVE(addr) \
    asm volatile("mbarrier.arrive.shared.b64 _, [%0];" :: "r"(addr) : "memory")

#define MBAR_WAIT(addr, parity) do {                                          \
    uint32_t _m = (addr), _p = (parity), _done;                               \
    asm volatile(                                                             \
        "{\n\t.reg .pred p;\n\t"                                              \
        "mbarrier.try_wait.parity.acquire.cta.shared::cta.b64 p, [%1], %2;\n\t"\
        "selp.b32 %0, 1, 0, p;\n\t}"                                          \
        : "=r"(_done) : "r"(_m), "r"(_p) : "memory");                         \
    if (!_done) {                                                             \
        asm volatile(                                                         \
            "{\n\t.reg .pred P1;\n\t"                                         \
            "WL_%=:\n\t"                                                      \
            "mbarrier.try_wait.parity.acquire.cta.shared::cta.b64 P1, [%0], %1, 0x989680;\n\t" \
            "@P1 bra.uni WD_%=;\n\t"                                          \
            "bra.uni WL_%=;\n\t"                                              \
            "WD_%=:\n\t}"                                                     \
            :: "r"(_m), "r"(_p) : "memory");                                  \
    }                                                                         \
} while (0)

#define BULK_G2S(dst_smem, src_gmem, bytes, mbar) \
    asm volatile("cp.async.bulk.shared::cluster.global.mbarrier::complete_tx::bytes " \
                 "[%0], [%1], %2, [%3];" \
                 :: "r"(dst_smem), "l"(src_gmem), "r"(bytes), "r"(mbar) : "memory")

__global__ void __launch_bounds__(256)
mlp_tma_kernel(const float* __restrict__ X, float* __restrict__ out, int nrows,
               const float* __restrict__ W1, const float* __restrict__ b1,
               const float* __restrict__ W2, const float* __restrict__ b2,
               const float* __restrict__ W3, const float* __restrict__ b3,
               const float* __restrict__ W4, const float* __restrict__ b4,
               const float* __restrict__ W5, const float* __restrict__ b5)
{
    extern __shared__ __align__(128) unsigned char smem[];
    __shared__ float s_weff[8];

    const int tid = threadIdx.x;
    const uint32_t sbase = smem_u32(smem);
    const uint32_t mbar0 = sbase + NSTAGE * STAGE_BYTES;   // full[i]@+16i, empty[i]@+16i+8

    const long long total_quads = (long long)(nrows >> 2);
    const long long nstages = (total_quads + STAGE_QUADS - 1) / STAGE_QUADS;

    if (tid == 0) {
        // init barriers
        #pragma unroll
        for (int i = 0; i < NSTAGE; i++) {
            MBAR_INIT(mbar0 + 16 * i,     1u);    // full: completed by TMA tx
            MBAR_INIT(mbar0 + 16 * i + 8, 256u);  // empty: all consumers arrive
        }
        asm volatile("fence.proxy.async.shared::cta;" ::: "memory");

        // prologue TMAs: first NSTAGE of this block's stages
        #pragma unroll
        for (int k = 0; k < NSTAGE; k++) {
            long long s = (long long)blockIdx.x + (long long)k * gridDim.x;
            if (s < nstages) {
                long long q0 = s * STAGE_QUADS;
                long long qn = total_quads - q0;
                uint32_t bytes = (uint32_t)((qn < STAGE_QUADS ? qn : STAGE_QUADS) * 112);
                MBAR_EXPECT_TX(mbar0 + 16 * k, bytes);
                BULK_G2S(sbase + k * STAGE_BYTES,
                         (const void*)(X + q0 * 28), bytes, mbar0 + 16 * k);
            }
        }

        // ---- compose (overlaps with in-flight TMAs) ----
        const float c50 = W5[0], c51 = W5[1];

        const float w45_0 = fmaf(W4[0], c50, W4[1] * c51);
        const float w45_1 = fmaf(W4[2], c50, W4[3] * c51);
        const float w45_2 = fmaf(W4[4], c50, W4[5] * c51);

        const float w345_0 = fmaf(W3[0],  w45_0, fmaf(W3[1],  w45_1, W3[2]  * w45_2));
        const float w345_1 = fmaf(W3[3],  w45_0, fmaf(W3[4],  w45_1, W3[5]  * w45_2));
        const float w345_2 = fmaf(W3[6],  w45_0, fmaf(W3[7],  w45_1, W3[8]  * w45_2));
        const float w345_3 = fmaf(W3[9],  w45_0, fmaf(W3[10], w45_1, W3[11] * w45_2));

        const float w2345_0 = fmaf(W2[0],  w345_0, fmaf(W2[1],  w345_1, fmaf(W2[2],  w345_2, W2[3]  * w345_3)));
        const float w2345_1 = fmaf(W2[4],  w345_0, fmaf(W2[5],  w345_1, fmaf(W2[6],  w345_2, W2[7]  * w345_3)));
        const float w2345_2 = fmaf(W2[8],  w345_0, fmaf(W2[9],  w345_1, fmaf(W2[10], w345_2, W2[11] * w345_3)));
        const float w2345_3 = fmaf(W2[12], w345_0, fmaf(W2[13], w345_1, fmaf(W2[14], w345_2, W2[15] * w345_3)));
        const float w2345_4 = fmaf(W2[16], w345_0, fmaf(W2[17], w345_1, fmaf(W2[18], w345_2, W2[19] * w345_3)));

        #pragma unroll
        for (int i = 0; i < 7; i++) {
            s_weff[i] = fmaf(W1[i*5 + 0], w2345_0,
                        fmaf(W1[i*5 + 1], w2345_1,
                        fmaf(W1[i*5 + 2], w2345_2,
                        fmaf(W1[i*5 + 3], w2345_3,
                             W1[i*5 + 4] * w2345_4))));
        }

        float be = b5[0];
        be = fmaf(b4[0], c50, be);
        be = fmaf(b4[1], c51, be);
        be = fmaf(b3[0], w45_0, be);
        be = fmaf(b3[1], w45_1, be);
        be = fmaf(b3[2], w45_2, be);
        be = fmaf(b2[0], w345_0, be);
        be = fmaf(b2[1], w345_1, be);
        be = fmaf(b2[2], w345_2, be);
        be = fmaf(b2[3], w345_3, be);
        be = fmaf(b1[0], w2345_0, be);
        be = fmaf(b1[1], w2345_1, be);
        be = fmaf(b1[2], w2345_2, be);
        be = fmaf(b1[3], w2345_3, be);
        be = fmaf(b1[4], w2345_4, be);
        s_weff[7] = be;
    }
    __syncthreads();

    const float w0 = s_weff[0], w1 = s_weff[1], w2 = s_weff[2], w3 = s_weff[3];
    const float w4 = s_weff[4], w5 = s_weff[5], w6 = s_weff[6], be = s_weff[7];

    float4* outv = reinterpret_cast<float4*>(out);

    int phase = 0;
    for (long long k = 0;; k++) {
        const long long s = (long long)blockIdx.x + k * gridDim.x;
        if (s >= nstages) break;
        const int slot = (int)(k & (NSTAGE - 1));
        const uint32_t full_b  = mbar0 + 16 * slot;
        const uint32_t empty_b = full_b + 8;

        MBAR_WAIT(full_b, phase);

        const long long q0 = s * STAGE_QUADS;
        const int quads = (int)((total_quads - q0 < STAGE_QUADS) ? (total_quads - q0)
                                                                 : STAGE_QUADS);
        if (tid < quads) {
            const float4* xq = reinterpret_cast<const float4*>(
                smem + (size_t)slot * STAGE_BYTES + (size_t)tid * 112);
            float4 p0 = xq[0], p1 = xq[1], p2 = xq[2], p3 = xq[3];
            float4 p4 = xq[4], p5 = xq[5], p6 = xq[6];

            float f[28];
            f[0]=p0.x; f[1]=p0.y; f[2]=p0.z; f[3]=p0.w;
            f[4]=p1.x; f[5]=p1.y; f[6]=p1.z; f[7]=p1.w;
            f[8]=p2.x; f[9]=p2.y; f[10]=p2.z; f[11]=p2.w;
            f[12]=p3.x; f[13]=p3.y; f[14]=p3.z; f[15]=p3.w;
            f[16]=p4.x; f[17]=p4.y; f[18]=p4.z; f[19]=p4.w;
            f[20]=p5.x; f[21]=p5.y; f[22]=p5.z; f[23]=p5.w;
            f[24]=p6.x; f[25]=p6.y; f[26]=p6.z; f[27]=p6.w;

            float r[4];
            #pragma unroll
            for (int r4 = 0; r4 < 4; r4++) {
                const float* x = f + r4 * 7;
                float z = be;
                z = fmaf(x[0], w0, z);
                z = fmaf(x[1], w1, z);
                z = fmaf(x[2], w2, z);
                z = fmaf(x[3], w3, z);
                z = fmaf(x[4], w4, z);
                z = fmaf(x[5], w5, z);
                z = fmaf(x[6], w6, z);
                r[r4] = 1.0f / (1.0f + __expf(-z));
            }

            float4 o;
            o.x = r[0]; o.y = r[1]; o.z = r[2]; o.w = r[3];
            __stcs(outv + q0 + tid, o);
        }

        MBAR_ARRIVE(empty_b);

        // producer: refill this slot for stage s + NSTAGE*gridDim (4 ahead)
        if (tid == 0) {
            const long long s2 = s + (long long)NSTAGE * gridDim.x;
            if (s2 < nstages) {
                MBAR_WAIT(empty_b, phase);   // all 256 consumed this slot
                const long long q2 = s2 * STAGE_QUADS;
                long long qn = total_quads - q2;
                uint32_t bytes = (uint32_t)((qn < STAGE_QUADS ? qn : STAGE_QUADS) * 112);
                MBAR_EXPECT_TX(full_b, bytes);
                BULK_G2S(sbase + slot * STAGE_BYTES,
                         (const void*)(X + q2 * 28), bytes, full_b);
            }
        }

        if (slot == NSTAGE - 1) phase ^= 1;
    }

    // Tail rows (nrows % 4) — zero for 4M rows; kept for safety.
    if (blockIdx.x == 0 && tid == 0) {
        for (long long rr = total_quads << 2; rr < nrows; rr++) {
            const float* x = X + rr * 7;
            float z = be;
            z = fmaf(x[0], w0, z);
            z = fmaf(x[1], w1, z);
            z = fmaf(x[2], w2, z);
            z = fmaf(x[3], w3, z);
            z = fmaf(x[4], w4, z);
            z = fmaf(x[5], w5, z);
            z = fmaf(x[6], w6, z);
            out[rr] = 1.0f / (1.0f + __expf(-z));
        }
    }
}

extern "C" void kernel_launch(void* const* d_in, const int* in_sizes, int n_in,
                              void* d_out, int out_size)
{
    const float* X  = (const float*)d_in[0];
    const float* W1 = (const float*)d_in[1];
    const float* b1 = (const float*)d_in[2];
    const float* W2 = (const float*)d_in[3];
    const float* b2 = (const float*)d_in[4];
    const float* W3 = (const float*)d_in[5];
    const float* b3 = (const float*)d_in[6];
    const float* W4 = (const float*)d_in[7];
    const float* b4 = (const float*)d_in[8];
    const float* W5 = (const float*)d_in[9];
    const float* b5 = (const float*)d_in[10];
    float* out = (float*)d_out;

    int nrows = in_sizes[0] / 7;

    const int smem_bytes = NSTAGE * STAGE_BYTES + NSTAGE * 16;  // buffers + barriers

    static bool attr_done = false;
    if (!attr_done) {
        cudaFuncSetAttribute(mlp_tma_kernel,
                             cudaFuncAttributeMaxDynamicSharedMemorySize, smem_bytes);
        attr_done = true;
    }

    int sms = 0;
    if (cudaDeviceGetAttribute(&sms, cudaDevAttrMultiProcessorCount, 0) != cudaSuccess || sms <= 0)
        sms = 148;

    mlp_tma_kernel<<<sms, 256, smem_bytes>>>(X, out, nrows,
                                             W1, b1, W2, b2, W3, b3, W4, b4, W5, b5);
}

// round 7
// speedup vs baseline: 1.3074x; 1.0804x over previous
#include <cuda_runtime.h>
#include <math.h>
#include <stdint.h>

// ---------------------------------------------------------------------------
// Persistent TMA-pipelined kernel, 2 blocks per SM for latency hiding.
//   Stage = 1024 rows = 28672 B. 3-deep mbarrier pipeline per block.
//   Producer (thread 0): cp.async.bulk HBM->SMEM (async proxy, no L1tex
//   wavefronts). Consumers (256 thr): 4 rows each via conflict-free LDS,
//   28 FMA + sigmoid, coalesced STG.128.
// ---------------------------------------------------------------------------

#define NSTAGE       3
#define STAGE_QUADS  256                    // row-quads per stage
#define STAGE_BYTES  (STAGE_QUADS * 112)    // 28672 B
#define BLOCKS_PER_SM 2

__device__ __forceinline__ uint32_t smem_u32(const void* p) {
    uint32_t a;
    asm("{ .reg .u64 t; cvta.to.shared.u64 t, %1; cvt.u32.u64 %0, t; }"
        : "=r"(a) : "l"(p));
    return a;
}

#define MBAR_INIT(addr, cnt) \
    asm volatile("mbarrier.init.shared.b64 [%0], %1;" :: "r"(addr), "r"(cnt) : "memory")

#define MBAR_EXPECT_TX(addr, bytes) \
    asm volatile("mbarrier.arrive.expect_tx.shared.b64 _, [%0], %1;" \
                 :: "r"(addr), "r"(bytes) : "memory")

#define MBAR_ARRIVE(addr) \
    asm volatile("mbarrier.arrive.shared.b64 _, [%0];" :: "r"(addr) : "memory")

#define MBAR_WAIT(addr, parity) do {                                          \
    uint32_t _m = (addr), _p = (parity), _done;                               \
    asm volatile(                                                             \
        "{\n\t.reg .pred p;\n\t"                                              \
        "mbarrier.try_wait.parity.acquire.cta.shared::cta.b64 p, [%1], %2;\n\t"\
        "selp.b32 %0, 1, 0, p;\n\t}"                                          \
        : "=r"(_done) : "r"(_m), "r"(_p) : "memory");                         \
    if (!_done) {                                                             \
        asm volatile(                                                         \
            "{\n\t.reg .pred P1;\n\t"                                         \
            "WL_%=:\n\t"                                                      \
            "mbarrier.try_wait.parity.acquire.cta.shared::cta.b64 P1, [%0], %1, 0x989680;\n\t" \
            "@P1 bra.uni WD_%=;\n\t"                                          \
            "bra.uni WL_%=;\n\t"                                              \
            "WD_%=:\n\t}"                                                     \
            :: "r"(_m), "r"(_p) : "memory");                                  \
    }                                                                         \
} while (0)

#define BULK_G2S(dst_smem, src_gmem, bytes, mbar) \
    asm volatile("cp.async.bulk.shared::cluster.global.mbarrier::complete_tx::bytes " \
                 "[%0], [%1], %2, [%3];" \
                 :: "r"(dst_smem), "l"(src_gmem), "r"(bytes), "r"(mbar) : "memory")

__global__ void __launch_bounds__(256)
mlp_tma2_kernel(const float* __restrict__ X, float* __restrict__ out, int nrows,
                const float* __restrict__ W1, const float* __restrict__ b1,
                const float* __restrict__ W2, const float* __restrict__ b2,
                const float* __restrict__ W3, const float* __restrict__ b3,
                const float* __restrict__ W4, const float* __restrict__ b4,
                const float* __restrict__ W5, const float* __restrict__ b5)
{
    extern __shared__ __align__(128) unsigned char smem[];
    __shared__ float s_weff[8];

    const int tid = threadIdx.x;
    const uint32_t sbase = smem_u32(smem);
    const uint32_t mbar0 = sbase + NSTAGE * STAGE_BYTES;   // full[i]@+16i, empty[i]@+16i+8

    const long long total_quads = (long long)(nrows >> 2);
    const long long nstages = (total_quads + STAGE_QUADS - 1) / STAGE_QUADS;

    if (tid == 0) {
        #pragma unroll
        for (int i = 0; i < NSTAGE; i++) {
            MBAR_INIT(mbar0 + 16 * i,     1u);    // full: completed by TMA tx
            MBAR_INIT(mbar0 + 16 * i + 8, 256u);  // empty: all consumers arrive
        }
        asm volatile("fence.proxy.async.shared::cta;" ::: "memory");

        // prologue TMAs: first NSTAGE of this block's stages
        #pragma unroll
        for (int k = 0; k < NSTAGE; k++) {
            long long s = (long long)blockIdx.x + (long long)k * gridDim.x;
            if (s < nstages) {
                long long q0 = s * STAGE_QUADS;
                long long qn = total_quads - q0;
                uint32_t bytes = (uint32_t)((qn < STAGE_QUADS ? qn : STAGE_QUADS) * 112);
                MBAR_EXPECT_TX(mbar0 + 16 * k, bytes);
                BULK_G2S(sbase + k * STAGE_BYTES,
                         (const void*)(X + q0 * 28), bytes, mbar0 + 16 * k);
            }
        }

        // ---- compose 5 linears into 7->1 affine (overlaps in-flight TMAs) ----
        const float c50 = W5[0], c51 = W5[1];

        const float w45_0 = fmaf(W4[0], c50, W4[1] * c51);
        const float w45_1 = fmaf(W4[2], c50, W4[3] * c51);
        const float w45_2 = fmaf(W4[4], c50, W4[5] * c51);

        const float w345_0 = fmaf(W3[0],  w45_0, fmaf(W3[1],  w45_1, W3[2]  * w45_2));
        const float w345_1 = fmaf(W3[3],  w45_0, fmaf(W3[4],  w45_1, W3[5]  * w45_2));
        const float w345_2 = fmaf(W3[6],  w45_0, fmaf(W3[7],  w45_1, W3[8]  * w45_2));
        const float w345_3 = fmaf(W3[9],  w45_0, fmaf(W3[10], w45_1, W3[11] * w45_2));

        const float w2345_0 = fmaf(W2[0],  w345_0, fmaf(W2[1],  w345_1, fmaf(W2[2],  w345_2, W2[3]  * w345_3)));
        const float w2345_1 = fmaf(W2[4],  w345_0, fmaf(W2[5],  w345_1, fmaf(W2[6],  w345_2, W2[7]  * w345_3)));
        const float w2345_2 = fmaf(W2[8],  w345_0, fmaf(W2[9],  w345_1, fmaf(W2[10], w345_2, W2[11] * w345_3)));
        const float w2345_3 = fmaf(W2[12], w345_0, fmaf(W2[13], w345_1, fmaf(W2[14], w345_2, W2[15] * w345_3)));
        const float w2345_4 = fmaf(W2[16], w345_0, fmaf(W2[17], w345_1, fmaf(W2[18], w345_2, W2[19] * w345_3)));

        #pragma unroll
        for (int i = 0; i < 7; i++) {
            s_weff[i] = fmaf(W1[i*5 + 0], w2345_0,
                        fmaf(W1[i*5 + 1], w2345_1,
                        fmaf(W1[i*5 + 2], w2345_2,
                        fmaf(W1[i*5 + 3], w2345_3,
                             W1[i*5 + 4] * w2345_4))));
        }

        float be = b5[0];
        be = fmaf(b4[0], c50, be);
        be = fmaf(b4[1], c51, be);
        be = fmaf(b3[0], w45_0, be);
        be = fmaf(b3[1], w45_1, be);
        be = fmaf(b3[2], w45_2, be);
        be = fmaf(b2[0], w345_0, be);
        be = fmaf(b2[1], w345_1, be);
        be = fmaf(b2[2], w345_2, be);
        be = fmaf(b2[3], w345_3, be);
        be = fmaf(b1[0], w2345_0, be);
        be = fmaf(b1[1], w2345_1, be);
        be = fmaf(b1[2], w2345_2, be);
        be = fmaf(b1[3], w2345_3, be);
        be = fmaf(b1[4], w2345_4, be);
        s_weff[7] = be;
    }
    __syncthreads();

    const float w0 = s_weff[0], w1 = s_weff[1], w2 = s_weff[2], w3 = s_weff[3];
    const float w4 = s_weff[4], w5 = s_weff[5], w6 = s_weff[6], be = s_weff[7];

    float4* outv = reinterpret_cast<float4*>(out);

    int phase = 0;
    int slot = 0;
    for (long long k = 0;; k++) {
        const long long s = (long long)blockIdx.x + k * gridDim.x;
        if (s >= nstages) break;
        const uint32_t full_b  = mbar0 + 16 * slot;
        const uint32_t empty_b = full_b + 8;

        MBAR_WAIT(full_b, phase);

        const long long q0 = s * STAGE_QUADS;
        const int quads = (int)((total_quads - q0 < STAGE_QUADS) ? (total_quads - q0)
                                                                 : STAGE_QUADS);
        if (tid < quads) {
            const float4* xq = reinterpret_cast<const float4*>(
                smem + (size_t)slot * STAGE_BYTES + (size_t)tid * 112);
            float4 p0 = xq[0], p1 = xq[1], p2 = xq[2], p3 = xq[3];
            float4 p4 = xq[4], p5 = xq[5], p6 = xq[6];

            float f[28];
            f[0]=p0.x; f[1]=p0.y; f[2]=p0.z; f[3]=p0.w;
            f[4]=p1.x; f[5]=p1.y; f[6]=p1.z; f[7]=p1.w;
            f[8]=p2.x; f[9]=p2.y; f[10]=p2.z; f[11]=p2.w;
            f[12]=p3.x; f[13]=p3.y; f[14]=p3.z; f[15]=p3.w;
            f[16]=p4.x; f[17]=p4.y; f[18]=p4.z; f[19]=p4.w;
            f[20]=p5.x; f[21]=p5.y; f[22]=p5.z; f[23]=p5.w;
            f[24]=p6.x; f[25]=p6.y; f[26]=p6.z; f[27]=p6.w;

            float r[4];
            #pragma unroll
            for (int r4 = 0; r4 < 4; r4++) {
                const float* x = f + r4 * 7;
                float z = be;
                z = fmaf(x[0], w0, z);
                z = fmaf(x[1], w1, z);
                z = fmaf(x[2], w2, z);
                z = fmaf(x[3], w3, z);
                z = fmaf(x[4], w4, z);
                z = fmaf(x[5], w5, z);
                z = fmaf(x[6], w6, z);
                r[r4] = 1.0f / (1.0f + __expf(-z));
            }

            float4 o;
            o.x = r[0]; o.y = r[1]; o.z = r[2]; o.w = r[3];
            __stcs(outv + q0 + tid, o);
        }

        MBAR_ARRIVE(empty_b);

        // producer: refill this slot for stage s + NSTAGE*gridDim (3 ahead)
        if (tid == 0) {
            const long long s2 = s + (long long)NSTAGE * gridDim.x;
            if (s2 < nstages) {
                MBAR_WAIT(empty_b, phase);   // all 256 consumed this slot
                const long long q2 = s2 * STAGE_QUADS;
                long long qn = total_quads - q2;
                uint32_t bytes = (uint32_t)((qn < STAGE_QUADS ? qn : STAGE_QUADS) * 112);
                MBAR_EXPECT_TX(full_b, bytes);
                BULK_G2S(sbase + slot * STAGE_BYTES,
                         (const void*)(X + q2 * 28), bytes, full_b);
            }
        }

        if (++slot == NSTAGE) { slot = 0; phase ^= 1; }
    }

    // Tail rows (nrows % 4) — zero for 4M rows; kept for safety.
    if (blockIdx.x == 0 && tid == 0) {
        for (long long rr = total_quads << 2; rr < nrows; rr++) {
            const float* x = X + rr * 7;
            float z = be;
            z = fmaf(x[0], w0, z);
            z = fmaf(x[1], w1, z);
            z = fmaf(x[2], w2, z);
            z = fmaf(x[3], w3, z);
            z = fmaf(x[4], w4, z);
            z = fmaf(x[5], w5, z);
            z = fmaf(x[6], w6, z);
            out[rr] = 1.0f / (1.0f + __expf(-z));
        }
    }
}

extern "C" void kernel_launch(void* const* d_in, const int* in_sizes, int n_in,
                              void* d_out, int out_size)
{
    const float* X  = (const float*)d_in[0];
    const float* W1 = (const float*)d_in[1];
    const float* b1 = (const float*)d_in[2];
    const float* W2 = (const float*)d_in[3];
    const float* b2 = (const float*)d_in[4];
    const float* W3 = (const float*)d_in[5];
    const float* b3 = (const float*)d_in[6];
    const float* W4 = (const float*)d_in[7];
    const float* b4 = (const float*)d_in[8];
    const float* W5 = (const float*)d_in[9];
    const float* b5 = (const float*)d_in[10];
    float* out = (float*)d_out;

    int nrows = in_sizes[0] / 7;

    const int smem_bytes = NSTAGE * STAGE_BYTES + NSTAGE * 16;  // 86064 B

    static bool attr_done = false;
    if (!attr_done) {
        cudaFuncSetAttribute(mlp_tma2_kernel,
                             cudaFuncAttributeMaxDynamicSharedMemorySize, smem_bytes);
        attr_done = true;
    }

    int sms = 0;
    if (cudaDeviceGetAttribute(&sms, cudaDevAttrMultiProcessorCount, 0) != cudaSuccess || sms <= 0)
        sms = 148;

    mlp_tma2_kernel<<<sms * BLOCKS_PER_SM, 256, smem_bytes>>>(
        X, out, nrows, W1, b1, W2, b2, W3, b3, W4, b4, W5, b5);
}